// round 16
// baseline (speedup 1.0000x reference)
#include <cuda_runtime.h>
#include <math.h>

typedef unsigned long long u64;

__device__ __forceinline__ u64 f2pk(float lo, float hi) {
    u64 r; asm("mov.b64 %0,{%1,%2};" : "=l"(r) : "f"(lo), "f"(hi)); return r;
}
__device__ __forceinline__ void f2upk(u64 a, float& lo, float& hi) {
    asm("mov.b64 {%0,%1},%2;" : "=f"(lo), "=f"(hi) : "l"(a));
}
__device__ __forceinline__ u64 f2add(u64 a, u64 b) {
    u64 d; asm("add.rn.f32x2 %0,%1,%2;" : "=l"(d) : "l"(a), "l"(b)); return d;
}
__device__ __forceinline__ u64 f2fma(u64 a, u64 b, u64 c) {
    u64 d; asm("fma.rn.f32x2 %0,%1,%2,%3;" : "=l"(d) : "l"(a), "l"(b), "l"(c)); return d;
}

// Fast tanh via MUFU.EX2 + fast divide. |rel err| ~1e-6. (validated R8-R15)
__device__ __forceinline__ float fast_tanh(float a) {
    float e = __expf(-2.0f * fabsf(a));
    float t = __fdividef(1.0f - e, 1.0f + e);
    return copysignf(t, a);
}

__global__ void __launch_bounds__(128, 1) matchnet_kernel(
    const float* __restrict__ X,
    const float* __restrict__ W1, const float* __restrict__ b1,
    const float* __restrict__ W2, const float* __restrict__ b2,
    const float* __restrict__ W3, const float* __restrict__ b3,
    const float* __restrict__ W4, const float* __restrict__ b4,
    float* __restrict__ out, int B)
{
    __shared__ __align__(16) float sW1[120];
    __shared__ __align__(16) float sW2[400];
    __shared__ __align__(16) float sW3[400];
    __shared__ __align__(16) float sW4[160];
    __shared__ __align__(16) float sb1[20], sb2s[20], sb3[20], sb4[8];

    const int t = threadIdx.x;
    const int idx = blockIdx.x * 128 + t;

    // ---- issue the bids load FIRST: its DRAM/L2 latency retires in the
    // shadow of weight staging + the barrier (grid*block == B, so every
    // thread reaches the barrier; the guard only predicates the load).
    float Z[6];
    bool active = (idx < B);
    if (active) {
        const float2* Xp = reinterpret_cast<const float2*>(X + (size_t)idx * 6);
        float2 a0 = Xp[0], a1 = Xp[1], a2 = Xp[2];
        Z[0] = a0.x; Z[1] = a0.y; Z[2] = a1.x; Z[3] = a1.y; Z[4] = a2.x; Z[5] = a2.y;
    }

    // ---- vectorized weight staging (float4; all W sizes are multiples of 4)
    {
        const float4* s; float4* d;
        s = reinterpret_cast<const float4*>(W1); d = reinterpret_cast<float4*>(sW1);
        if (t < 30) d[t] = s[t];
        s = reinterpret_cast<const float4*>(W2); d = reinterpret_cast<float4*>(sW2);
        if (t < 100) d[t] = s[t];
        s = reinterpret_cast<const float4*>(W3); d = reinterpret_cast<float4*>(sW3);
        if (t < 100) d[t] = s[t];
        s = reinterpret_cast<const float4*>(W4); d = reinterpret_cast<float4*>(sW4);
        if (t < 40) d[t] = s[t];
    }
    // ---- vectorized bias staging on disjoint thread groups (one round)
    if (t < 5) {
        reinterpret_cast<float4*>(sb1)[t] = reinterpret_cast<const float4*>(b1)[t];
    } else if (t >= 8 && t < 13) {
        reinterpret_cast<float4*>(sb2s)[t - 8] = reinterpret_cast<const float4*>(b2)[t - 8];
    } else if (t >= 16 && t < 21) {
        reinterpret_cast<float4*>(sb3)[t - 16] = reinterpret_cast<const float4*>(b3)[t - 16];
    } else if (t >= 24 && t < 26) {
        reinterpret_cast<float4*>(sb4)[t - 24] = reinterpret_cast<const float4*>(b4)[t - 24];
    }
    __syncthreads();

    if (!active) return;

    // ---- MLP 6->20->20->20->8 (fast tanh) ----
    float h1[20], h2[20];
#pragma unroll
    for (int o = 0; o < 20; ++o) {
        const float2* w = reinterpret_cast<const float2*>(&sW1[o * 6]);
        float2 w0 = w[0], w1 = w[1], w2 = w[2];
        float a = sb1[o];
        a = fmaf(w0.x, Z[0], a); a = fmaf(w0.y, Z[1], a);
        a = fmaf(w1.x, Z[2], a); a = fmaf(w1.y, Z[3], a);
        a = fmaf(w2.x, Z[4], a); a = fmaf(w2.y, Z[5], a);
        h1[o] = fast_tanh(a);
    }
#pragma unroll
    for (int o = 0; o < 20; ++o) {
        const float4* w = reinterpret_cast<const float4*>(&sW2[o * 20]);
        float a = sb2s[o];
#pragma unroll
        for (int qq = 0; qq < 5; ++qq) {
            float4 wq = w[qq];
            a = fmaf(wq.x, h1[qq * 4 + 0], a);
            a = fmaf(wq.y, h1[qq * 4 + 1], a);
            a = fmaf(wq.z, h1[qq * 4 + 2], a);
            a = fmaf(wq.w, h1[qq * 4 + 3], a);
        }
        h2[o] = fast_tanh(a);
    }
#pragma unroll
    for (int o = 0; o < 20; ++o) {
        const float4* w = reinterpret_cast<const float4*>(&sW3[o * 20]);
        float a = sb3[o];
#pragma unroll
        for (int qq = 0; qq < 5; ++qq) {
            float4 wq = w[qq];
            a = fmaf(wq.x, h2[qq * 4 + 0], a);
            a = fmaf(wq.y, h2[qq * 4 + 1], a);
            a = fmaf(wq.z, h2[qq * 4 + 2], a);
            a = fmaf(wq.w, h2[qq * 4 + 3], a);
        }
        h1[o] = fast_tanh(a);
    }
    float z[8];
#pragma unroll
    for (int o = 0; o < 8; ++o) {
        const float4* w = reinterpret_cast<const float4*>(&sW4[o * 20]);
        float a = sb4[o];
#pragma unroll
        for (int qq = 0; qq < 5; ++qq) {
            float4 wq = w[qq];
            a = fmaf(wq.x, h1[qq * 4 + 0], a);
            a = fmaf(wq.y, h1[qq * 4 + 1], a);
            a = fmaf(wq.z, h1[qq * 4 + 2], a);
            a = fmaf(wq.w, h1[qq * 4 + 3], a);
        }
        z[o] = fast_tanh(a);
    }

    // ---- PDHG QP (packed f32x2), duals scaled by tau:
    //      L2' = tau*l2 packed; m = -tau*l1 scalar  (validated session-best body)
    const float tau  = 0.9f / sqrtf(26.0f);
    const float tau2 = tau * tau;
    const u64 NEG1 = 0xBF800000BF800000ULL;
    const u64 NT2  = f2pk(-tau2, -tau2);

    u64 zp[4], czp[4], xp[4], l2p[4];
#pragma unroll
    for (int k = 0; k < 4; ++k) {
        float zl = z[2 * k], zh = z[2 * k + 1];
        zp[k]  = f2pk(zl, zh);
        czp[k] = f2pk(tau - zl, tau - zh);
        xp[k]  = f2pk(fmaxf(zl, 0.0f), fmaxf(zh, 0.0f));
        l2p[k] = 0ULL;
    }
    u64 sb2p[3];
    sb2p[0] = f2pk(tau2 * Z[0], tau2 * Z[1]);
    sb2p[1] = f2pk(tau2 * Z[2], tau2 * Z[3]);
    sb2p[2] = f2pk(tau2 * Z[4], tau2 * Z[5]);
    float m0 = 0.f, m1 = 0.f, m2 = 0.f, m3 = 0.f, m4 = 0.f, m5 = 0.f;

#pragma unroll 1
    for (int it = 0; it < 150; ++it) {
        // sv'' = -tau * S^T l1 (<=0), packed pairs
        // cols: 0:{0,3} 1:{1,4} 2:{2,5} 3:{0,1,5} 4:{2,3,5} 5:{0,3} 6:{1,4} 7:{2,4}
        u64 s01 = f2add(f2pk(m0, m1), f2pk(m3, m4));       // (sv0, sv1)
        float t01 = m0 + m1;
        u64 s23 = f2add(f2pk(m2, t01), f2pk(m5, m5));      // (sv2, sv3)
        float t23 = m2 + m3;
        float sv4 = t23 + m5;
        float sv0, sv1; f2upk(s01, sv0, sv1);
        u64 s45 = f2pk(sv4, sv0);                          // (sv4, sv5=sv0)
        u64 s67 = f2add(f2pk(m1, m2), f2pk(m4, m4));       // (sv6=sv1, sv7)

        // v = (x + cz) + (L2' + sv'')
        u64 v0 = f2add(f2add(xp[0], czp[0]), f2add(l2p[0], s01));
        u64 v1 = f2add(f2add(xp[1], czp[1]), f2add(l2p[1], s23));
        u64 v2 = f2add(f2add(xp[2], czp[2]), f2add(l2p[2], s45));
        u64 v3 = f2add(f2add(xp[3], czp[3]), f2add(l2p[3], s67));

        // ||v||^2 scalar (unpacks are alu-pipe movs)
        float f0, f1, f2, f3, f4, f5, f6, f7;
        f2upk(v0, f0, f1); f2upk(v1, f2, f3);
        f2upk(v2, f4, f5); f2upk(v3, f6, f7);
        float c0 = f0 * f0;
        c0 = fmaf(f1, f1, c0); c0 = fmaf(f2, f2, c0); c0 = fmaf(f3, f3, c0);
        float c1 = f4 * f4;
        c1 = fmaf(f5, f5, c1); c1 = fmaf(f6, f6, c1); c1 = fmaf(f7, f7, c1);
        float ss = c0 + c1;

        // scale = max(1 - tau/||v||, 0); rsqrt(0)=inf -> clamps to 0
        float r = rsqrtf(ss);
        float scale = fmaxf(fmaf(-tau, r, 1.0f), 0.0f);
        u64 sc2 = f2pk(scale, scale);

        // xn = z + scale*v ; xb = 2*xn - x
        u64 xn0 = f2fma(v0, sc2, zp[0]);
        u64 xn1 = f2fma(v1, sc2, zp[1]);
        u64 xn2 = f2fma(v2, sc2, zp[2]);
        u64 xn3 = f2fma(v3, sc2, zp[3]);
        u64 xb0 = f2add(xn0, f2fma(xp[0], NEG1, xn0));
        u64 xb1 = f2add(xn1, f2fma(xp[1], NEG1, xn1));
        u64 xb2 = f2add(xn2, f2fma(xp[2], NEG1, xn2));
        u64 xb3 = f2add(xn3, f2fma(xp[3], NEG1, xn3));
        xp[0] = xn0; xp[1] = xn1; xp[2] = xn2; xp[3] = xn3;

        float e0, e1, e2, e3, e4, e5, e6, e7;
        f2upk(xb0, e0, e1); f2upk(xb1, e2, e3);
        f2upk(xb2, e4, e5); f2upk(xb3, e6, e7);

        // rr = S @ xb, rows: 0:{0,3,5} 1:{1,3,6} 2:{2,4,7} 3:{0,4,5} 4:{1,6,7} 5:{2,3,4}
        u64 pp = f2add(xb0, f2pk(e5, e6));                 // (p05, p16)
        float p05, p16; f2upk(pp, p05, p16);
        float p24 = e2 + e4;
        u64 rr01 = f2add(pp, f2pk(e3, e3));                // (rr0, rr1)
        u64 rr23 = f2add(f2pk(p24, p05), f2pk(e7, e4));    // (rr2, rr3)
        u64 rr45 = f2add(f2pk(p16, p24), f2pk(e7, e3));    // (rr4, rr5)

        // l1 dual (negated, scaled): m = min(m - tau2*rr + tau2*b, 0)
        u64 u01 = f2add(f2fma(rr01, NT2, f2pk(m0, m1)), sb2p[0]);
        u64 u23 = f2add(f2fma(rr23, NT2, f2pk(m2, m3)), sb2p[1]);
        u64 u45 = f2add(f2fma(rr45, NT2, f2pk(m4, m5)), sb2p[2]);
        float q0, q1, q2, q3, q4, q5;
        f2upk(u01, q0, q1); f2upk(u23, q2, q3); f2upk(u45, q4, q5);
        m0 = fminf(q0, 0.0f); m1 = fminf(q1, 0.0f); m2 = fminf(q2, 0.0f);
        m3 = fminf(q3, 0.0f); m4 = fminf(q4, 0.0f); m5 = fminf(q5, 0.0f);

        // l2 dual (scaled): L2' = max(L2' - tau2*xb, 0)
        {
            u64 w0 = f2fma(xb0, NT2, l2p[0]);
            u64 w1 = f2fma(xb1, NT2, l2p[1]);
            u64 w2 = f2fma(xb2, NT2, l2p[2]);
            u64 w3 = f2fma(xb3, NT2, l2p[3]);
            float a, b;
            f2upk(w0, a, b); l2p[0] = f2pk(fmaxf(a, 0.f), fmaxf(b, 0.f));
            f2upk(w1, a, b); l2p[1] = f2pk(fmaxf(a, 0.f), fmaxf(b, 0.f));
            f2upk(w2, a, b); l2p[2] = f2pk(fmaxf(a, 0.f), fmaxf(b, 0.f));
            f2upk(w3, a, b); l2p[3] = f2pk(fmaxf(a, 0.f), fmaxf(b, 0.f));
        }
    }

    // ---- store ----
    float o0, o1, o2, o3, o4, o5, o6, o7;
    f2upk(xp[0], o0, o1); f2upk(xp[1], o2, o3);
    f2upk(xp[2], o4, o5); f2upk(xp[3], o6, o7);
    float4* op = reinterpret_cast<float4*>(out + (size_t)idx * 8);
    op[0] = make_float4(o0, o1, o2, o3);
    op[1] = make_float4(o4, o5, o6, o7);
}

extern "C" void kernel_launch(void* const* d_in, const int* in_sizes, int n_in,
                              void* d_out, int out_size)
{
    const float* X  = (const float*)d_in[0];
    const float* W1 = (const float*)d_in[1];
    const float* b1 = (const float*)d_in[2];
    const float* W2 = (const float*)d_in[3];
    const float* b2 = (const float*)d_in[4];
    const float* W3 = (const float*)d_in[5];
    const float* b3 = (const float*)d_in[6];
    const float* W4 = (const float*)d_in[7];
    const float* b4 = (const float*)d_in[8];

    const int B = in_sizes[0] / 6;
    float* out = (float*)d_out;

    const int block = 128;
    const int grid = (B + block - 1) / block;
    matchnet_kernel<<<grid, block>>>(X, W1, b1, W2, b2, W3, b3, W4, b4, out, B);
}

// round 17
// speedup vs baseline: 1.0691x; 1.0691x over previous
#include <cuda_runtime.h>
#include <math.h>

typedef unsigned long long u64;

__device__ __forceinline__ u64 f2pk(float lo, float hi) {
    u64 r; asm("mov.b64 %0,{%1,%2};" : "=l"(r) : "f"(lo), "f"(hi)); return r;
}
__device__ __forceinline__ void f2upk(u64 a, float& lo, float& hi) {
    asm("mov.b64 {%0,%1},%2;" : "=f"(lo), "=f"(hi) : "l"(a));
}
__device__ __forceinline__ u64 f2add(u64 a, u64 b) {
    u64 d; asm("add.rn.f32x2 %0,%1,%2;" : "=l"(d) : "l"(a), "l"(b)); return d;
}
__device__ __forceinline__ u64 f2fma(u64 a, u64 b, u64 c) {
    u64 d; asm("fma.rn.f32x2 %0,%1,%2,%3;" : "=l"(d) : "l"(a), "l"(b), "l"(c)); return d;
}

// Fast tanh via MUFU.EX2 + fast divide. |rel err| ~1e-6. (validated R8-R16)
__device__ __forceinline__ float fast_tanh(float a) {
    float e = __expf(-2.0f * fabsf(a));
    float t = __fdividef(1.0f - e, 1.0f + e);
    return copysignf(t, a);
}

__global__ void __launch_bounds__(128, 1) matchnet_kernel(
    const float* __restrict__ X,
    const float* __restrict__ W1, const float* __restrict__ b1,
    const float* __restrict__ W2, const float* __restrict__ b2,
    const float* __restrict__ W3, const float* __restrict__ b3,
    const float* __restrict__ W4, const float* __restrict__ b4,
    float* __restrict__ out, int B)
{
    __shared__ __align__(16) float sW1[120];
    __shared__ __align__(16) float sW2[400];
    __shared__ __align__(16) float sW3[400];
    __shared__ __align__(16) float sW4[160];
    __shared__ float sb1[20], sb2s[20], sb3[20], sb4[8];

    const int t = threadIdx.x;
    // Vectorized weight staging (all W arrays are multiples of 4 floats).
    {
        const float4* s; float4* d;
        s = reinterpret_cast<const float4*>(W1); d = reinterpret_cast<float4*>(sW1);
        if (t < 30) d[t] = s[t];
        s = reinterpret_cast<const float4*>(W2); d = reinterpret_cast<float4*>(sW2);
        if (t < 100) d[t] = s[t];
        s = reinterpret_cast<const float4*>(W3); d = reinterpret_cast<float4*>(sW3);
        if (t < 100) d[t] = s[t];
        s = reinterpret_cast<const float4*>(W4); d = reinterpret_cast<float4*>(sW4);
        if (t < 40) d[t] = s[t];
    }
    if (t < 20) { sb1[t] = b1[t]; sb2s[t] = b2[t]; sb3[t] = b3[t]; }
    if (t < 8)  { sb4[t] = b4[t]; }
    __syncthreads();

    const int idx = blockIdx.x * 128 + t;
    if (idx >= B) return;

    // ---- load bids Z ----
    float Z[6];
    {
        const float2* Xp = reinterpret_cast<const float2*>(X + (size_t)idx * 6);
        float2 a0 = Xp[0], a1 = Xp[1], a2 = Xp[2];
        Z[0] = a0.x; Z[1] = a0.y; Z[2] = a1.x; Z[3] = a1.y; Z[4] = a2.x; Z[5] = a2.y;
    }

    // ---- MLP 6->20->20->20->8 (fast tanh) ----
    float h1[20], h2[20];
#pragma unroll
    for (int o = 0; o < 20; ++o) {
        const float2* w = reinterpret_cast<const float2*>(&sW1[o * 6]);
        float2 w0 = w[0], w1 = w[1], w2 = w[2];
        float a = sb1[o];
        a = fmaf(w0.x, Z[0], a); a = fmaf(w0.y, Z[1], a);
        a = fmaf(w1.x, Z[2], a); a = fmaf(w1.y, Z[3], a);
        a = fmaf(w2.x, Z[4], a); a = fmaf(w2.y, Z[5], a);
        h1[o] = fast_tanh(a);
    }
#pragma unroll
    for (int o = 0; o < 20; ++o) {
        const float4* w = reinterpret_cast<const float4*>(&sW2[o * 20]);
        float a = sb2s[o];
#pragma unroll
        for (int qq = 0; qq < 5; ++qq) {
            float4 wq = w[qq];
            a = fmaf(wq.x, h1[qq * 4 + 0], a);
            a = fmaf(wq.y, h1[qq * 4 + 1], a);
            a = fmaf(wq.z, h1[qq * 4 + 2], a);
            a = fmaf(wq.w, h1[qq * 4 + 3], a);
        }
        h2[o] = fast_tanh(a);
    }
#pragma unroll
    for (int o = 0; o < 20; ++o) {
        const float4* w = reinterpret_cast<const float4*>(&sW3[o * 20]);
        float a = sb3[o];
#pragma unroll
        for (int qq = 0; qq < 5; ++qq) {
            float4 wq = w[qq];
            a = fmaf(wq.x, h2[qq * 4 + 0], a);
            a = fmaf(wq.y, h2[qq * 4 + 1], a);
            a = fmaf(wq.z, h2[qq * 4 + 2], a);
            a = fmaf(wq.w, h2[qq * 4 + 3], a);
        }
        h1[o] = fast_tanh(a);
    }
    float z[8];
#pragma unroll
    for (int o = 0; o < 8; ++o) {
        const float4* w = reinterpret_cast<const float4*>(&sW4[o * 20]);
        float a = sb4[o];
#pragma unroll
        for (int qq = 0; qq < 5; ++qq) {
            float4 wq = w[qq];
            a = fmaf(wq.x, h1[qq * 4 + 0], a);
            a = fmaf(wq.y, h1[qq * 4 + 1], a);
            a = fmaf(wq.z, h1[qq * 4 + 2], a);
            a = fmaf(wq.w, h1[qq * 4 + 3], a);
        }
        z[o] = fast_tanh(a);
    }

    // ---- PDHG QP (packed f32x2), duals scaled by tau:
    //      L2' = tau*l2 packed; m = -tau*l1 scalar  (session-best body)
    const float tau  = 0.9f / sqrtf(26.0f);
    const float tau2 = tau * tau;
    const u64 NEG1 = 0xBF800000BF800000ULL;
    const u64 NT2  = f2pk(-tau2, -tau2);

    u64 zp[4], czp[4], xp[4], l2p[4];
#pragma unroll
    for (int k = 0; k < 4; ++k) {
        float zl = z[2 * k], zh = z[2 * k + 1];
        zp[k]  = f2pk(zl, zh);
        czp[k] = f2pk(tau - zl, tau - zh);
        xp[k]  = f2pk(fmaxf(zl, 0.0f), fmaxf(zh, 0.0f));
        l2p[k] = 0ULL;
    }
    u64 sb2p[3];
    sb2p[0] = f2pk(tau2 * Z[0], tau2 * Z[1]);
    sb2p[1] = f2pk(tau2 * Z[2], tau2 * Z[3]);
    sb2p[2] = f2pk(tau2 * Z[4], tau2 * Z[5]);
    float m0 = 0.f, m1 = 0.f, m2 = 0.f, m3 = 0.f, m4 = 0.f, m5 = 0.f;

#pragma unroll 1
    for (int it = 0; it < 150; ++it) {
        // sv'' = -tau * S^T l1 (<=0), packed pairs
        // cols: 0:{0,3} 1:{1,4} 2:{2,5} 3:{0,1,5} 4:{2,3,5} 5:{0,3} 6:{1,4} 7:{2,4}
        u64 s01 = f2add(f2pk(m0, m1), f2pk(m3, m4));       // (sv0, sv1)
        float t01 = m0 + m1;
        u64 s23 = f2add(f2pk(m2, t01), f2pk(m5, m5));      // (sv2, sv3)
        float t23 = m2 + m3;
        float sv4 = t23 + m5;
        float sv0, sv1; f2upk(s01, sv0, sv1);
        u64 s45 = f2pk(sv4, sv0);                          // (sv4, sv5=sv0)
        u64 s67 = f2add(f2pk(m1, m2), f2pk(m4, m4));       // (sv6=sv1, sv7)

        // v = (x + cz) + (L2' + sv'')
        u64 v0 = f2add(f2add(xp[0], czp[0]), f2add(l2p[0], s01));
        u64 v1 = f2add(f2add(xp[1], czp[1]), f2add(l2p[1], s23));
        u64 v2 = f2add(f2add(xp[2], czp[2]), f2add(l2p[2], s45));
        u64 v3 = f2add(f2add(xp[3], czp[3]), f2add(l2p[3], s67));

        // ||v||^2 scalar (unpacks are alu-pipe movs)
        float f0, f1, f2, f3, f4, f5, f6, f7;
        f2upk(v0, f0, f1); f2upk(v1, f2, f3);
        f2upk(v2, f4, f5); f2upk(v3, f6, f7);
        float c0 = f0 * f0;
        c0 = fmaf(f1, f1, c0); c0 = fmaf(f2, f2, c0); c0 = fmaf(f3, f3, c0);
        float c1 = f4 * f4;
        c1 = fmaf(f5, f5, c1); c1 = fmaf(f6, f6, c1); c1 = fmaf(f7, f7, c1);
        float ss = c0 + c1;

        // scale = max(1 - tau/||v||, 0); rsqrt(0)=inf -> clamps to 0
        float r = rsqrtf(ss);
        float scale = fmaxf(fmaf(-tau, r, 1.0f), 0.0f);
        u64 sc2 = f2pk(scale, scale);

        // xn = z + scale*v ; xb = 2*xn - x
        u64 xn0 = f2fma(v0, sc2, zp[0]);
        u64 xn1 = f2fma(v1, sc2, zp[1]);
        u64 xn2 = f2fma(v2, sc2, zp[2]);
        u64 xn3 = f2fma(v3, sc2, zp[3]);
        u64 xb0 = f2add(xn0, f2fma(xp[0], NEG1, xn0));
        u64 xb1 = f2add(xn1, f2fma(xp[1], NEG1, xn1));
        u64 xb2 = f2add(xn2, f2fma(xp[2], NEG1, xn2));
        u64 xb3 = f2add(xn3, f2fma(xp[3], NEG1, xn3));
        xp[0] = xn0; xp[1] = xn1; xp[2] = xn2; xp[3] = xn3;

        float e0, e1, e2, e3, e4, e5, e6, e7;
        f2upk(xb0, e0, e1); f2upk(xb1, e2, e3);
        f2upk(xb2, e4, e5); f2upk(xb3, e6, e7);

        // rr = S @ xb, rows: 0:{0,3,5} 1:{1,3,6} 2:{2,4,7} 3:{0,4,5} 4:{1,6,7} 5:{2,3,4}
        u64 pp = f2add(xb0, f2pk(e5, e6));                 // (p05, p16)
        float p05, p16; f2upk(pp, p05, p16);
        float p24 = e2 + e4;
        u64 rr01 = f2add(pp, f2pk(e3, e3));                // (rr0, rr1)
        u64 rr23 = f2add(f2pk(p24, p05), f2pk(e7, e4));    // (rr2, rr3)
        u64 rr45 = f2add(f2pk(p16, p24), f2pk(e7, e3));    // (rr4, rr5)

        // l1 dual (negated, scaled): m = min(m - tau2*rr + tau2*b, 0)
        u64 u01 = f2add(f2fma(rr01, NT2, f2pk(m0, m1)), sb2p[0]);
        u64 u23 = f2add(f2fma(rr23, NT2, f2pk(m2, m3)), sb2p[1]);
        u64 u45 = f2add(f2fma(rr45, NT2, f2pk(m4, m5)), sb2p[2]);
        float q0, q1, q2, q3, q4, q5;
        f2upk(u01, q0, q1); f2upk(u23, q2, q3); f2upk(u45, q4, q5);
        m0 = fminf(q0, 0.0f); m1 = fminf(q1, 0.0f); m2 = fminf(q2, 0.0f);
        m3 = fminf(q3, 0.0f); m4 = fminf(q4, 0.0f); m5 = fminf(q5, 0.0f);

        // l2 dual (scaled): L2' = max(L2' - tau2*xb, 0)
        {
            u64 w0 = f2fma(xb0, NT2, l2p[0]);
            u64 w1 = f2fma(xb1, NT2, l2p[1]);
            u64 w2 = f2fma(xb2, NT2, l2p[2]);
            u64 w3 = f2fma(xb3, NT2, l2p[3]);
            float a, b;
            f2upk(w0, a, b); l2p[0] = f2pk(fmaxf(a, 0.f), fmaxf(b, 0.f));
            f2upk(w1, a, b); l2p[1] = f2pk(fmaxf(a, 0.f), fmaxf(b, 0.f));
            f2upk(w2, a, b); l2p[2] = f2pk(fmaxf(a, 0.f), fmaxf(b, 0.f));
            f2upk(w3, a, b); l2p[3] = f2pk(fmaxf(a, 0.f), fmaxf(b, 0.f));
        }
    }

    // ---- store ----
    float o0, o1, o2, o3, o4, o5, o6, o7;
    f2upk(xp[0], o0, o1); f2upk(xp[1], o2, o3);
    f2upk(xp[2], o4, o5); f2upk(xp[3], o6, o7);
    float4* op = reinterpret_cast<float4*>(out + (size_t)idx * 8);
    op[0] = make_float4(o0, o1, o2, o3);
    op[1] = make_float4(o4, o5, o6, o7);
}

extern "C" void kernel_launch(void* const* d_in, const int* in_sizes, int n_in,
                              void* d_out, int out_size)
{
    const float* X  = (const float*)d_in[0];
    const float* W1 = (const float*)d_in[1];
    const float* b1 = (const float*)d_in[2];
    const float* W2 = (const float*)d_in[3];
    const float* b2 = (const float*)d_in[4];
    const float* W3 = (const float*)d_in[5];
    const float* b3 = (const float*)d_in[6];
    const float* W4 = (const float*)d_in[7];
    const float* b4 = (const float*)d_in[8];

    const int B = in_sizes[0] / 6;
    float* out = (float*)d_out;

    const int block = 128;
    const int grid = (B + block - 1) / block;
    matchnet_kernel<<<grid, block>>>(X, W1, b1, W2, b2, W3, b3, W4, b4, out, B);
}